// round 6
// baseline (speedup 1.0000x reference)
#include <cuda_runtime.h>
#include <cuda_bf16.h>
#include <math.h>
#include <stdint.h>

#define H_DIM 2048
#define E_NUM 16
#define TOPKN 6
#define I_DIM 1408
#define SH_DIM 2816
#define T_TOK 4096

#define NASSIGN (T_TOK*TOPKN)              /* 24576 */
#define MAXEXTRA 512
#define NASS_MAX (NASSIGN + MAXEXTRA)      /* 25088 */

#define BM 128
#define BN 128
#define BK 32
#define PADROWS (NASS_MAX + E_NUM*BM)      /* 27136 */
#define MAXTILES (NASS_MAX/BM + E_NUM)     /* 212 */
#define HEDGE_REL 1e-5

// ---------------- scratch (static device globals: no allocation) ----------------
__device__ int   d_topi[NASS_MAX];
__device__ float d_topw[NASS_MAX];
__device__ int   d_atok[NASS_MAX];
__device__ int   d_nExtra;
__device__ int   d_counts[E_NUM];
__device__ int   d_fill[E_NUM];
__device__ int   d_start[E_NUM];
__device__ int   d_tileE[MAXTILES];
__device__ int   d_tileR[MAXTILES];
__device__ int   d_numTiles;
__device__ int   d_assign[PADROWS];
__device__ float d_yg[(size_t)PADROWS * I_DIM];    // routed gate buf (becomes y after swiglu)
__device__ float d_yu[(size_t)PADROWS * I_DIM];    // routed up buf
__device__ float d_yshg[(size_t)T_TOK * SH_DIM];   // shared gate buf (becomes y)
__device__ float d_yshu[(size_t)T_TOK * SH_DIM];   // shared up buf

// ---------------- init ----------------
__global__ void init_kernel() {
    int i = blockIdx.x * blockDim.x + threadIdx.x;
    if (i == 0) d_nExtra = 0;
    if (i < E_NUM) { d_counts[i] = 0; d_fill[i] = 0; }
    if (i < PADROWS) d_assign[i] = -1;
}

// ---- gate: fp64 logits -> softmax -> top-7 -> boundary hedge -> renorm (R4, passing) ----
__global__ void gate_kernel(const float* __restrict__ x, const float* __restrict__ gw) {
    int t    = (blockIdx.x * blockDim.x + threadIdx.x) >> 5;
    int lane = threadIdx.x & 31;
    if (t >= T_TOK) return;
    const float* xr = x + (size_t)t * H_DIM;
    double acc[E_NUM];
#pragma unroll
    for (int e = 0; e < E_NUM; e++) acc[e] = 0.0;
    for (int h = lane; h < H_DIM; h += 32) {
        double xv = (double)xr[h];
#pragma unroll
        for (int e = 0; e < E_NUM; e++) acc[e] += xv * (double)gw[e * H_DIM + h];
    }
#pragma unroll
    for (int e = 0; e < E_NUM; e++) {
#pragma unroll
        for (int off = 16; off; off >>= 1)
            acc[e] += __shfl_xor_sync(0xffffffffu, acc[e], off);
    }
    if (lane == 0) {
        double mx = acc[0];
#pragma unroll
        for (int e = 1; e < E_NUM; e++) mx = acc[e] > mx ? acc[e] : mx;
        double s[E_NUM]; double sum = 0.0;
#pragma unroll
        for (int e = 0; e < E_NUM; e++) { s[e] = exp(acc[e] - mx); sum += s[e]; }
        double inv = 1.0 / sum;
#pragma unroll
        for (int e = 0; e < E_NUM; e++) s[e] *= inv;
        bool used[E_NUM];
#pragma unroll
        for (int e = 0; e < E_NUM; e++) used[e] = false;
        int idx[7]; double val[7];
        for (int k = 0; k < 7; k++) {
            int best = -1; double bv = -1.0;
            for (int e = 0; e < E_NUM; e++)
                if (!used[e] && s[e] > bv) { bv = s[e]; best = e; }
            used[best] = true; idx[k] = best; val[k] = bv;
        }
        double w5 = 0.0;
        for (int k = 0; k < 5; k++) w5 += val[k];
        bool hedge = (val[5] - val[6]) < HEDGE_REL * val[5];
        if (hedge) {
            double m = 0.5 * (val[5] + val[6]);
            double W = w5 + m + 1e-20;
            for (int k = 0; k < 5; k++) {
                d_topi[t * TOPKN + k] = idx[k];
                d_topw[t * TOPKN + k] = (float)(val[k] / W);
                d_atok[t * TOPKN + k] = t;
                atomicAdd(&d_counts[idx[k]], 1);
            }
            float hw = (float)(0.5 * m / W);
            d_topi[t * TOPKN + 5] = idx[5];
            d_topw[t * TOPKN + 5] = hw;
            d_atok[t * TOPKN + 5] = t;
            atomicAdd(&d_counts[idx[5]], 1);
            int j = atomicAdd(&d_nExtra, 1);
            if (j < MAXEXTRA) {
                d_topi[NASSIGN + j] = idx[6];
                d_topw[NASSIGN + j] = hw;
                d_atok[NASSIGN + j] = t;
                atomicAdd(&d_counts[idx[6]], 1);
            }
        } else {
            double W = w5 + val[5] + 1e-20;
            for (int k = 0; k < TOPKN; k++) {
                d_topi[t * TOPKN + k] = idx[k];
                d_topw[t * TOPKN + k] = (float)(val[k] / W);
                d_atok[t * TOPKN + k] = t;
                atomicAdd(&d_counts[idx[k]], 1);
            }
        }
    }
}

// ---------------- scan + scatter ----------------
__global__ void scan_kernel() {
    int off = 0, nt = 0;
    for (int e = 0; e < E_NUM; e++) {
        d_start[e] = off;
        int tiles = (d_counts[e] + BM - 1) / BM;
        for (int j = 0; j < tiles; j++) { d_tileE[nt] = e; d_tileR[nt] = off + j * BM; nt++; }
        off += tiles * BM;
    }
    d_numTiles = nt;
}

__global__ void scatter_kernel() {
    int a = blockIdx.x * blockDim.x + threadIdx.x;
    int total = NASSIGN + min(d_nExtra, MAXEXTRA);
    if (a >= total) return;
    int e = d_topi[a];
    int pos = atomicAdd(&d_fill[e], 1);
    d_assign[d_start[e] + pos] = a;
}

// ---------------- bf16x3 helpers ----------------
__device__ __forceinline__ void splitpack(float4 v, uint32_t& h01, uint32_t& h23,
                                          uint32_t& l01, uint32_t& l23) {
    __nv_bfloat16 hx = __float2bfloat16_rn(v.x);
    __nv_bfloat16 hy = __float2bfloat16_rn(v.y);
    __nv_bfloat16 hz = __float2bfloat16_rn(v.z);
    __nv_bfloat16 hw = __float2bfloat16_rn(v.w);
    __nv_bfloat16 lx = __float2bfloat16_rn(v.x - __bfloat162float(hx));
    __nv_bfloat16 ly = __float2bfloat16_rn(v.y - __bfloat162float(hy));
    __nv_bfloat16 lz = __float2bfloat16_rn(v.z - __bfloat162float(hz));
    __nv_bfloat16 lw = __float2bfloat16_rn(v.w - __bfloat162float(hw));
    h01 = (uint32_t)__bfloat16_as_ushort(hx) | ((uint32_t)__bfloat16_as_ushort(hy) << 16);
    h23 = (uint32_t)__bfloat16_as_ushort(hz) | ((uint32_t)__bfloat16_as_ushort(hw) << 16);
    l01 = (uint32_t)__bfloat16_as_ushort(lx) | ((uint32_t)__bfloat16_as_ushort(ly) << 16);
    l23 = (uint32_t)__bfloat16_as_ushort(lz) | ((uint32_t)__bfloat16_as_ushort(lw) << 16);
}

__device__ __forceinline__ void mma_bf16(float* c, const uint32_t* a, const uint32_t* b) {
    asm volatile(
        "mma.sync.aligned.m16n8k16.row.col.f32.bf16.bf16.f32 "
        "{%0,%1,%2,%3}, {%4,%5,%6,%7}, {%8,%9}, {%0,%1,%2,%3};"
        : "+f"(c[0]), "+f"(c[1]), "+f"(c[2]), "+f"(c[3])
        : "r"(a[0]), "r"(a[1]), "r"(a[2]), "r"(a[3]), "r"(b[0]), "r"(b[1]));
}

// ---------------- unified bf16x3 tensor-core GEMM ----------------
// C[m][n] = sum_k A[m][k] * B[n][k]
// MODE 0: routed gate/up: A = x gathered by token, B quant (K=2048), C = d_yg/d_yu (which)
// MODE 1: routed down:    A = d_yg rows,           B quant (K=1408), C = atomicAdd out[token]
// MODE 2: shared gate/up: A = x contiguous,        B float (K=2048), C = d_yshg/d_yshu
// MODE 3: shared down:    A = d_yshg,              B float (K=2816), C = store out
template<int MODE>
__global__ __launch_bounds__(256) void gemm_kernel(
    const float* __restrict__ Ain,
    const int* __restrict__ Bq, const float* __restrict__ Bsc, const float* __restrict__ Bze,
    const float* __restrict__ Bf,
    float* __restrict__ Cout, int which)
{
    constexpr int KDIM = (MODE == 0 || MODE == 2) ? 2048 : (MODE == 1 ? 1408 : 2816);
    constexpr int NG = KDIM / 64;
    constexpr int LDC = (MODE == 0) ? I_DIM : (MODE == 2 ? SH_DIM : H_DIM);

    const float* A = (MODE == 1) ? d_yg : (MODE == 3) ? d_yshg : Ain;
    float* C = (MODE == 0) ? (which ? d_yu : d_yg)
             : (MODE == 2) ? (which ? d_yshu : d_yshg)
             : Cout;

    extern __shared__ uint32_t smem[];   // A: [2][4096], B: [2][4096] uint32 (64KB)
    __shared__ int sTok[BM];

    int tile = blockIdx.x;
    int row0, ebase = 0;
    if (MODE == 0 || MODE == 1) {
        if (tile >= d_numTiles) return;
        row0 = d_tileR[tile];
        ebase = d_tileE[tile] * ((MODE == 0) ? I_DIM : H_DIM);
    } else {
        row0 = tile * BM;
    }
    int n0 = blockIdx.y * BN;
    int tid = threadIdx.x;
    int lane = tid & 31;
    int warp = tid >> 5;
    int wm = warp & 1, wn = warp >> 1;   // 2 x 4 warp grid, 64x32 warp tile

    if (MODE == 0 || MODE == 1) {
        for (int i = tid; i < BM; i += 256) {
            int a = d_assign[row0 + i];
            sTok[i] = (a >= 0) ? d_atok[a] : -1;
        }
        __syncthreads();
    }

    // per-thread loader geometry
    const int kq = (tid & 7) * 4;          // k-offset of this thread's float4 within BK
    const int fk_w = kq >> 4;
    const int kk_w = kq & 15;
    const int t0_w = (kk_w & 7) >> 1;
    const int khalf = kk_w >> 3;

    float4 av[4], wv[4];

    auto loadGlobal = [&](int k0) {
#pragma unroll
        for (int j = 0; j < 4; j++) {
            int m = (tid >> 3) + j * 32;
            if (MODE == 0) {
                int tok = sTok[m];
                av[j] = (tok >= 0) ? *(const float4*)(A + (size_t)tok * 2048 + k0 + kq)
                                   : make_float4(0.f, 0.f, 0.f, 0.f);
            } else {
                av[j] = *(const float4*)(A + (size_t)(row0 + m) * KDIM + k0 + kq);
            }
        }
        int grp = k0 >> 6;
#pragma unroll
        for (int j = 0; j < 4; j++) {
            int n = (tid >> 3) + j * 32;
            if (MODE <= 1) {
                size_t brow = (size_t)(ebase + n0 + n);
                int4 q = *(const int4*)(Bq + brow * KDIM + k0 + kq);
                float s = Bsc[brow * NG + grp];
                float z = Bze[brow * NG + grp];
                wv[j] = make_float4(((float)q.x - z) * s, ((float)q.y - z) * s,
                                    ((float)q.z - z) * s, ((float)q.w - z) * s);
            } else {
                wv[j] = *(const float4*)(Bf + (size_t)(n0 + n) * KDIM + k0 + kq);
            }
        }
    };

    auto storeStage = [&](int stg) {
        uint32_t* As_ = smem + stg * 4096;
        uint32_t* Bs2 = smem + 8192 + stg * 4096;
#pragma unroll
        for (int j = 0; j < 4; j++) {
            int m = (tid >> 3) + j * 32;
            int fm = m >> 4, mm = m & 15, gg = mm & 7;
            int slot = (mm >> 3) + (khalf << 1);
            int lane0 = gg * 4 + t0_w;
            uint32_t h01, h23, l01, l23;
            splitpack(av[j], h01, h23, l01, l23);
            int baseH = ((fk_w * 8 + fm) * 2 + 0) * 128;
            int baseL = ((fk_w * 8 + fm) * 2 + 1) * 128;
            As_[baseH + lane0 * 4 + slot] = h01;
            As_[baseH + (lane0 + 1) * 4 + slot] = h23;
            As_[baseL + lane0 * 4 + slot] = l01;
            As_[baseL + (lane0 + 1) * 4 + slot] = l23;
        }
#pragma unroll
        for (int j = 0; j < 4; j++) {
            int n = (tid >> 3) + j * 32;
            int fn = n >> 3, gg = n & 7;
            int lane0 = gg * 4 + t0_w;
            uint32_t h01, h23, l01, l23;
            splitpack(wv[j], h01, h23, l01, l23);
            int baseH = ((fk_w * 16 + fn) * 2 + 0) * 64;
            int baseL = ((fk_w * 16 + fn) * 2 + 1) * 64;
            Bs2[baseH + lane0 * 2 + khalf] = h01;
            Bs2[baseH + (lane0 + 1) * 2 + khalf] = h23;
            Bs2[baseL + lane0 * 2 + khalf] = l01;
            Bs2[baseL + (lane0 + 1) * 2 + khalf] = l23;
        }
    };

    float c[4][4][4];
#pragma unroll
    for (int i = 0; i < 4; i++)
#pragma unroll
        for (int j = 0; j < 4; j++)
#pragma unroll
            for (int k = 0; k < 4; k++) c[i][j][k] = 0.f;

    loadGlobal(0);
    storeStage(0);
    __syncthreads();

    const int KT = KDIM / BK;
    for (int kt = 0; kt < KT; kt++) {
        int stg = kt & 1;
        if (kt + 1 < KT) loadGlobal((kt + 1) * BK);

        const uint32_t* As_ = smem + stg * 4096;
        const uint32_t* Bs2 = smem + 8192 + stg * 4096;
#pragma unroll
        for (int fk = 0; fk < 2; fk++) {
            uint32_t a[4][2][4], b[4][2][2];
#pragma unroll
            for (int fm = 0; fm < 4; fm++)
#pragma unroll
                for (int pl = 0; pl < 2; pl++) {
                    uint4 v = *(const uint4*)&As_[((fk * 8 + wm * 4 + fm) * 2 + pl) * 128 + lane * 4];
                    a[fm][pl][0] = v.x; a[fm][pl][1] = v.y; a[fm][pl][2] = v.z; a[fm][pl][3] = v.w;
                }
#pragma unroll
            for (int fn = 0; fn < 4; fn++)
#pragma unroll
                for (int pl = 0; pl < 2; pl++) {
                    uint2 v = *(const uint2*)&Bs2[((fk * 16 + wn * 4 + fn) * 2 + pl) * 64 + lane * 2];
                    b[fn][pl][0] = v.x; b[fn][pl][1] = v.y;
                }
#pragma unroll
            for (int fm = 0; fm < 4; fm++)
#pragma unroll
                for (int fn = 0; fn < 4; fn++) {
                    mma_bf16(c[fm][fn], a[fm][0], b[fn][0]);   // hi*hi
                    mma_bf16(c[fm][fn], a[fm][0], b[fn][1]);   // hi*lo
                    mma_bf16(c[fm][fn], a[fm][1], b[fn][0]);   // lo*hi
                }
        }
        if (kt + 1 < KT) storeStage(stg ^ 1);
        __syncthreads();
    }

    // epilogue
    int g = lane >> 2, t = lane & 3;
#pragma unroll
    for (int fm = 0; fm < 4; fm++) {
        int mloc = wm * 64 + fm * 16 + g;
#pragma unroll
        for (int fn = 0; fn < 4; fn++) {
            int col = n0 + wn * 32 + fn * 8 + 2 * t;
            float* cc = c[fm][fn];
            if (MODE == 1) {
                int tk0 = sTok[mloc], tk1 = sTok[mloc + 8];
                if (tk0 >= 0) {
                    atomicAdd(&Cout[(size_t)tk0 * H_DIM + col], cc[0]);
                    atomicAdd(&Cout[(size_t)tk0 * H_DIM + col + 1], cc[1]);
                }
                if (tk1 >= 0) {
                    atomicAdd(&Cout[(size_t)tk1 * H_DIM + col], cc[2]);
                    atomicAdd(&Cout[(size_t)tk1 * H_DIM + col + 1], cc[3]);
                }
            } else {
                size_t r0 = (size_t)(row0 + mloc) * LDC + col;
                size_t r1 = (size_t)(row0 + mloc + 8) * LDC + col;
                *(float2*)&C[r0] = make_float2(cc[0], cc[1]);
                *(float2*)&C[r1] = make_float2(cc[2], cc[3]);
            }
        }
    }
}

// ---------------- elementwise SwiGLU ----------------
__global__ void swiglu_routed() {
    size_t i = (size_t)blockIdx.x * 256 + threadIdx.x;
    size_t total = (size_t)PADROWS * (I_DIM / 4);
    if (i >= total) return;
    int row = (int)(i / (I_DIM / 4));
    int col = (int)(i % (I_DIM / 4)) * 4;
    float4* pg = (float4*)&d_yg[(size_t)row * I_DIM + col];
    int a = d_assign[row];
    if (a < 0) { *pg = make_float4(0.f, 0.f, 0.f, 0.f); return; }
    float w = d_topw[a];
    float4 g = *pg;
    float4 u = *(const float4*)&d_yu[(size_t)row * I_DIM + col];
    g.x = (g.x / (1.f + expf(-g.x))) * u.x * w;
    g.y = (g.y / (1.f + expf(-g.y))) * u.y * w;
    g.z = (g.z / (1.f + expf(-g.z))) * u.z * w;
    g.w = (g.w / (1.f + expf(-g.w))) * u.w * w;
    *pg = g;
}

__global__ void swiglu_shared() {
    size_t i = (size_t)blockIdx.x * 256 + threadIdx.x;
    size_t total = (size_t)T_TOK * (SH_DIM / 4);
    if (i >= total) return;
    float4* pg = (float4*)&d_yshg[i * 4];
    float4 g = *pg;
    float4 u = *(const float4*)&d_yshu[i * 4];
    g.x = (g.x / (1.f + expf(-g.x))) * u.x;
    g.y = (g.y / (1.f + expf(-g.y))) * u.y;
    g.z = (g.z / (1.f + expf(-g.z))) * u.z;
    g.w = (g.w / (1.f + expf(-g.w))) * u.w;
    *pg = g;
}

// ---------------- launch ----------------
extern "C" void kernel_launch(void* const* d_in, const int* in_sizes, int n_in,
                              void* d_out, int out_size) {
    const float* x   = (const float*)d_in[0];
    const float* gw  = (const float*)d_in[1];
    const int*   wqg = (const int*)d_in[2];
    const float* sg  = (const float*)d_in[3];
    const float* zg  = (const float*)d_in[4];
    const int*   wqu = (const int*)d_in[5];
    const float* su  = (const float*)d_in[6];
    const float* zu  = (const float*)d_in[7];
    const int*   wqd = (const int*)d_in[8];
    const float* sd  = (const float*)d_in[9];
    const float* zd  = (const float*)d_in[10];
    const float* wgs = (const float*)d_in[11];
    const float* wus = (const float*)d_in[12];
    const float* wds = (const float*)d_in[13];
    float* out = (float*)d_out;

    const int SMEM = 65536;
    cudaFuncSetAttribute(gemm_kernel<0>, cudaFuncAttributeMaxDynamicSharedMemorySize, SMEM);
    cudaFuncSetAttribute(gemm_kernel<1>, cudaFuncAttributeMaxDynamicSharedMemorySize, SMEM);
    cudaFuncSetAttribute(gemm_kernel<2>, cudaFuncAttributeMaxDynamicSharedMemorySize, SMEM);
    cudaFuncSetAttribute(gemm_kernel<3>, cudaFuncAttributeMaxDynamicSharedMemorySize, SMEM);

    init_kernel<<<(PADROWS + 255) / 256, 256>>>();
    gate_kernel<<<(T_TOK * 32 + 127) / 128, 128>>>(x, gw);
    scan_kernel<<<1, 1>>>();
    scatter_kernel<<<(NASS_MAX + 255) / 256, 256>>>();

    // shared expert: gate, up -> swiglu -> down (plain store covers all of out)
    gemm_kernel<2><<<dim3(T_TOK / BM, SH_DIM / BN), 256, SMEM>>>(x, nullptr, nullptr, nullptr, wgs, nullptr, 0);
    gemm_kernel<2><<<dim3(T_TOK / BM, SH_DIM / BN), 256, SMEM>>>(x, nullptr, nullptr, nullptr, wus, nullptr, 1);
    {
        size_t tot = (size_t)T_TOK * (SH_DIM / 4);
        swiglu_shared<<<(unsigned)((tot + 255) / 256), 256>>>();
    }
    gemm_kernel<3><<<dim3(T_TOK / BM, H_DIM / BN), 256, SMEM>>>(nullptr, nullptr, nullptr, nullptr, wds, out, 0);

    // routed experts: gate, up -> swiglu(+combine weight) -> down (atomicAdd on out)
    gemm_kernel<0><<<dim3(MAXTILES, I_DIM / BN), 256, SMEM>>>(x, wqg, sg, zg, nullptr, nullptr, 0);
    gemm_kernel<0><<<dim3(MAXTILES, I_DIM / BN), 256, SMEM>>>(x, wqu, su, zu, nullptr, nullptr, 1);
    {
        size_t tot = (size_t)PADROWS * (I_DIM / 4);
        swiglu_routed<<<(unsigned)((tot + 255) / 256), 256>>>();
    }
    gemm_kernel<1><<<dim3(MAXTILES, H_DIM / BN), 256, SMEM>>>(nullptr, wqd, sd, zd, nullptr, out, 0);
}

// round 8
// speedup vs baseline: 1.2847x; 1.2847x over previous
#include <cuda_runtime.h>
#include <cuda_bf16.h>
#include <math.h>
#include <stdint.h>

#define H_DIM 2048
#define E_NUM 16
#define TOPKN 6
#define I_DIM 1408
#define SH_DIM 2816
#define T_TOK 4096

#define NASSIGN (T_TOK*TOPKN)
#define MAXEXTRA 512
#define NASS_MAX (NASSIGN + MAXEXTRA)
#define BM 128
#define BN 128
#define BK 32
#define PADROWS (NASS_MAX + E_NUM*BM)
#define MAXTILES (NASS_MAX/BM + E_NUM)
#define HEDGE_REL 1e-5

typedef __nv_bfloat16 bf16;

// ---------------- scratch ----------------
__device__ int   d_topi[NASS_MAX];
__device__ float d_topw[NASS_MAX];
__device__ int   d_atok[NASS_MAX];
__device__ int   d_nExtra;
__device__ int   d_counts[E_NUM];
__device__ int   d_fill[E_NUM];
__device__ int   d_start[E_NUM];
__device__ int   d_tileE[MAXTILES];
__device__ int   d_tileR[MAXTILES];
__device__ int   d_numTiles;
__device__ int   d_assign[PADROWS];
__device__ float d_yg[(size_t)PADROWS * I_DIM];
__device__ float d_yu[(size_t)PADROWS * I_DIM];
__device__ float d_yshg[(size_t)T_TOK * SH_DIM];
__device__ float d_yshu[(size_t)T_TOK * SH_DIM];
// bf16 hi/lo planes
__device__ bf16 d_xh[(size_t)T_TOK*H_DIM],  d_xl[(size_t)T_TOK*H_DIM];
__device__ bf16 d_whg[(size_t)E_NUM*I_DIM*H_DIM], d_wlg[(size_t)E_NUM*I_DIM*H_DIM];
__device__ bf16 d_whu[(size_t)E_NUM*I_DIM*H_DIM], d_wlu[(size_t)E_NUM*I_DIM*H_DIM];
__device__ bf16 d_whd[(size_t)E_NUM*H_DIM*I_DIM], d_wld[(size_t)E_NUM*H_DIM*I_DIM];
__device__ bf16 d_shgh[(size_t)SH_DIM*H_DIM], d_shgl[(size_t)SH_DIM*H_DIM];
__device__ bf16 d_shuh[(size_t)SH_DIM*H_DIM], d_shul[(size_t)SH_DIM*H_DIM];
__device__ bf16 d_shdh[(size_t)H_DIM*SH_DIM], d_shdl[(size_t)H_DIM*SH_DIM];
__device__ bf16 d_yh[(size_t)PADROWS*I_DIM],  d_yl[(size_t)PADROWS*I_DIM];
__device__ bf16 d_yshh[(size_t)T_TOK*SH_DIM], d_yshl[(size_t)T_TOK*SH_DIM];

// ---------------- init ----------------
__global__ void init_kernel() {
    int i = blockIdx.x * blockDim.x + threadIdx.x;
    if (i == 0) d_nExtra = 0;
    if (i < E_NUM) { d_counts[i] = 0; d_fill[i] = 0; }
    if (i < PADROWS) d_assign[i] = -1;
}

// ---- gate: fp64 logits -> softmax -> top-7 -> boundary hedge (passing, unchanged) ----
__global__ void gate_kernel(const float* __restrict__ x, const float* __restrict__ gw) {
    int t    = (blockIdx.x * blockDim.x + threadIdx.x) >> 5;
    int lane = threadIdx.x & 31;
    if (t >= T_TOK) return;
    const float* xr = x + (size_t)t * H_DIM;
    double acc[E_NUM];
#pragma unroll
    for (int e = 0; e < E_NUM; e++) acc[e] = 0.0;
    for (int h = lane; h < H_DIM; h += 32) {
        double xv = (double)xr[h];
#pragma unroll
        for (int e = 0; e < E_NUM; e++) acc[e] += xv * (double)gw[e * H_DIM + h];
    }
#pragma unroll
    for (int e = 0; e < E_NUM; e++) {
#pragma unroll
        for (int off = 16; off; off >>= 1)
            acc[e] += __shfl_xor_sync(0xffffffffu, acc[e], off);
    }
    if (lane == 0) {
        double mx = acc[0];
#pragma unroll
        for (int e = 1; e < E_NUM; e++) mx = acc[e] > mx ? acc[e] : mx;
        double s[E_NUM]; double sum = 0.0;
#pragma unroll
        for (int e = 0; e < E_NUM; e++) { s[e] = exp(acc[e] - mx); sum += s[e]; }
        double inv = 1.0 / sum;
#pragma unroll
        for (int e = 0; e < E_NUM; e++) s[e] *= inv;
        bool used[E_NUM];
#pragma unroll
        for (int e = 0; e < E_NUM; e++) used[e] = false;
        int idx[7]; double val[7];
        for (int k = 0; k < 7; k++) {
            int best = -1; double bv = -1.0;
            for (int e = 0; e < E_NUM; e++)
                if (!used[e] && s[e] > bv) { bv = s[e]; best = e; }
            used[best] = true; idx[k] = best; val[k] = bv;
        }
        double w5 = 0.0;
        for (int k = 0; k < 5; k++) w5 += val[k];
        bool hedge = (val[5] - val[6]) < HEDGE_REL * val[5];
        if (hedge) {
            double m = 0.5 * (val[5] + val[6]);
            double W = w5 + m + 1e-20;
            for (int k = 0; k < 5; k++) {
                d_topi[t * TOPKN + k] = idx[k];
                d_topw[t * TOPKN + k] = (float)(val[k] / W);
                d_atok[t * TOPKN + k] = t;
                atomicAdd(&d_counts[idx[k]], 1);
            }
            float hw = (float)(0.5 * m / W);
            d_topi[t * TOPKN + 5] = idx[5];
            d_topw[t * TOPKN + 5] = hw;
            d_atok[t * TOPKN + 5] = t;
            atomicAdd(&d_counts[idx[5]], 1);
            int j = atomicAdd(&d_nExtra, 1);
            if (j < MAXEXTRA) {
                d_topi[NASSIGN + j] = idx[6];
                d_topw[NASSIGN + j] = hw;
                d_atok[NASSIGN + j] = t;
                atomicAdd(&d_counts[idx[6]], 1);
            }
        } else {
            double W = w5 + val[5] + 1e-20;
            for (int k = 0; k < TOPKN; k++) {
                d_topi[t * TOPKN + k] = idx[k];
                d_topw[t * TOPKN + k] = (float)(val[k] / W);
                d_atok[t * TOPKN + k] = t;
                atomicAdd(&d_counts[idx[k]], 1);
            }
        }
    }
}

__global__ void scan_kernel() {
    int off = 0, nt = 0;
    for (int e = 0; e < E_NUM; e++) {
        d_start[e] = off;
        int tiles = (d_counts[e] + BM - 1) / BM;
        for (int j = 0; j < tiles; j++) { d_tileE[nt] = e; d_tileR[nt] = off + j * BM; nt++; }
        off += tiles * BM;
    }
    d_numTiles = nt;
}

__global__ void scatter_kernel() {
    int a = blockIdx.x * blockDim.x + threadIdx.x;
    int total = NASSIGN + min(d_nExtra, MAXEXTRA);
    if (a >= total) return;
    int e = d_topi[a];
    int pos = atomicAdd(&d_fill[e], 1);
    d_assign[d_start[e] + pos] = a;
}

// ---------------- split helpers ----------------
__device__ __forceinline__ uint32_t pack2(bf16 a, bf16 b) {
    return (uint32_t)__bfloat16_as_ushort(a) | ((uint32_t)__bfloat16_as_ushort(b) << 16);
}
__device__ __forceinline__ void split4(const float* v, uint2& h, uint2& l) {
    bf16 hh[4], ll[4];
#pragma unroll
    for (int i = 0; i < 4; i++) {
        hh[i] = __float2bfloat16_rn(v[i]);
        ll[i] = __float2bfloat16_rn(v[i] - __bfloat162float(hh[i]));
    }
    h = make_uint2(pack2(hh[0], hh[1]), pack2(hh[2], hh[3]));
    l = make_uint2(pack2(ll[0], ll[1]), pack2(ll[2], ll[3]));
}

// ---------------- one-shot conversion kernels ----------------
// Destination planes are selected INSIDE device code (device globals cannot be
// passed as args from host code — that was the R7 bug).
template<int WQ>  // 0: gate(K=2048)  1: up(K=2048)  2: down(K=1408)
__global__ void conv_quant(const int* __restrict__ q, const float* __restrict__ sc,
                           const float* __restrict__ ze) {
    constexpr int K = (WQ == 2) ? I_DIM : H_DIM;
    constexpr size_t TOTAL4 = (size_t)E_NUM * I_DIM * H_DIM / 4;
    bf16* ph = (WQ == 0) ? d_whg : (WQ == 1) ? d_whu : d_whd;
    bf16* pl = (WQ == 0) ? d_wlg : (WQ == 1) ? d_wlu : d_wld;
    size_t i = (size_t)blockIdx.x * 256 + threadIdx.x;
    if (i >= TOTAL4) return;
    size_t base = i * 4;
    size_t row = base / K;
    int k = (int)(base % K);
    size_t sIdx = row * (K >> 6) + (k >> 6);
    float s = sc[sIdx], z = ze[sIdx];
    int4 qq = *(const int4*)(q + base);
    float v[4] = { ((float)qq.x - z) * s, ((float)qq.y - z) * s,
                   ((float)qq.z - z) * s, ((float)qq.w - z) * s };
    uint2 h, l; split4(v, h, l);
    *(uint2*)(ph + base) = h;
    *(uint2*)(pl + base) = l;
}

template<int WF>  // 0: x  1: wg_shared  2: wu_shared  3: wd_shared
__global__ void conv_float(const float* __restrict__ f) {
    constexpr size_t TOTAL4 = (WF == 0) ? (size_t)T_TOK * H_DIM / 4
                                        : (size_t)SH_DIM * H_DIM / 4;
    bf16* ph = (WF == 0) ? d_xh : (WF == 1) ? d_shgh : (WF == 2) ? d_shuh : d_shdh;
    bf16* pl = (WF == 0) ? d_xl : (WF == 1) ? d_shgl : (WF == 2) ? d_shul : d_shdl;
    size_t i = (size_t)blockIdx.x * 256 + threadIdx.x;
    if (i >= TOTAL4) return;
    size_t base = i * 4;
    float4 vv = *(const float4*)(f + base);
    float v[4] = { vv.x, vv.y, vv.z, vv.w };
    uint2 h, l; split4(v, h, l);
    *(uint2*)(ph + base) = h;
    *(uint2*)(pl + base) = l;
}

__device__ __forceinline__ void mma_bf16(float* c, const uint32_t* a, const uint32_t* b) {
    asm volatile(
        "mma.sync.aligned.m16n8k16.row.col.f32.bf16.bf16.f32 "
        "{%0,%1,%2,%3}, {%4,%5,%6,%7}, {%8,%9}, {%0,%1,%2,%3};"
        : "+f"(c[0]), "+f"(c[1]), "+f"(c[2]), "+f"(c[3])
        : "r"(a[0]), "r"(a[1]), "r"(a[2]), "r"(a[3]), "r"(b[0]), "r"(b[1]));
}

// ---------------- unified bf16x3 tensor-core GEMM (planes pre-split) ----------------
template<int MODE>
__global__ __launch_bounds__(256) void gemm_kernel(float* __restrict__ Cout, int which) {
    constexpr int KDIM = (MODE == 0 || MODE == 2) ? 2048 : (MODE == 1 ? 1408 : 2816);
    constexpr int LDC = (MODE == 0) ? I_DIM : (MODE == 2 ? SH_DIM : H_DIM);

    const bf16* Ah = (MODE == 1) ? d_yh : (MODE == 3) ? d_yshh : d_xh;
    const bf16* Al = (MODE == 1) ? d_yl : (MODE == 3) ? d_yshl : d_xl;
    const bf16* Bh = (MODE == 0) ? (which ? d_whu : d_whg)
                   : (MODE == 1) ? d_whd
                   : (MODE == 2) ? (which ? d_shuh : d_shgh) : d_shdh;
    const bf16* Bl = (MODE == 0) ? (which ? d_wlu : d_wlg)
                   : (MODE == 1) ? d_wld
                   : (MODE == 2) ? (which ? d_shul : d_shgl) : d_shdl;
    float* C = (MODE == 0) ? (which ? d_yu : d_yg)
             : (MODE == 2) ? (which ? d_yshu : d_yshg) : Cout;

    extern __shared__ uint32_t smem[];
    __shared__ int sTok[BM];

    int tile = blockIdx.x;
    int row0; size_t ebase = 0;
    if (MODE == 0 || MODE == 1) {
        if (tile >= d_numTiles) return;
        row0 = d_tileR[tile];
        ebase = (size_t)d_tileE[tile] * ((MODE == 0) ? I_DIM : H_DIM);
    } else {
        row0 = tile * BM;
    }
    int n0 = blockIdx.y * BN;
    int tid = threadIdx.x;
    int lane = tid & 31;
    int warp = tid >> 5;
    int wm = warp & 1, wn = warp >> 1;

    if (MODE == 0 || MODE == 1) {
        for (int i = tid; i < BM; i += 256) {
            int a = d_assign[row0 + i];
            sTok[i] = (a >= 0) ? d_atok[a] : -1;
        }
        __syncthreads();
    }

    const int kq = (tid & 7) * 4;
    const int fk_w = kq >> 4;
    const int kk_w = kq & 15;
    const int t0_w = (kk_w & 7) >> 1;
    const int khalf = kk_w >> 3;

    uint2 avh[4], avl[4], wvh[4], wvl[4];

    auto loadGlobal = [&](int k0) {
#pragma unroll
        for (int j = 0; j < 4; j++) {
            int m = (tid >> 3) + j * 32;
            if (MODE == 0) {
                int tok = sTok[m];
                if (tok >= 0) {
                    size_t off = (size_t)tok * 2048 + k0 + kq;
                    avh[j] = *(const uint2*)(Ah + off);
                    avl[j] = *(const uint2*)(Al + off);
                } else { avh[j] = make_uint2(0, 0); avl[j] = make_uint2(0, 0); }
            } else {
                size_t off = (size_t)(row0 + m) * KDIM + k0 + kq;
                avh[j] = *(const uint2*)(Ah + off);
                avl[j] = *(const uint2*)(Al + off);
            }
        }
#pragma unroll
        for (int j = 0; j < 4; j++) {
            int n = (tid >> 3) + j * 32;
            size_t off = (ebase + n0 + n) * KDIM + k0 + kq;
            wvh[j] = *(const uint2*)(Bh + off);
            wvl[j] = *(const uint2*)(Bl + off);
        }
    };

    auto storeStage = [&](int stg) {
        uint32_t* As_ = smem + stg * 4096;
        uint32_t* Bs2 = smem + 8192 + stg * 4096;
#pragma unroll
        for (int j = 0; j < 4; j++) {
            int m = (tid >> 3) + j * 32;
            int fm = m >> 4, mm = m & 15, gg = mm & 7;
            int slot = (mm >> 3) + (khalf << 1);
            int lane0 = gg * 4 + t0_w;
            int baseH = ((fk_w * 8 + fm) * 2 + 0) * 128;
            int baseL = ((fk_w * 8 + fm) * 2 + 1) * 128;
            As_[baseH + lane0 * 4 + slot] = avh[j].x;
            As_[baseH + (lane0 + 1) * 4 + slot] = avh[j].y;
            As_[baseL + lane0 * 4 + slot] = avl[j].x;
            As_[baseL + (lane0 + 1) * 4 + slot] = avl[j].y;
        }
#pragma unroll
        for (int j = 0; j < 4; j++) {
            int n = (tid >> 3) + j * 32;
            int fn = n >> 3, gg = n & 7;
            int lane0 = gg * 4 + t0_w;
            int baseH = ((fk_w * 16 + fn) * 2 + 0) * 64;
            int baseL = ((fk_w * 16 + fn) * 2 + 1) * 64;
            Bs2[baseH + lane0 * 2 + khalf] = wvh[j].x;
            Bs2[baseH + (lane0 + 1) * 2 + khalf] = wvh[j].y;
            Bs2[baseL + lane0 * 2 + khalf] = wvl[j].x;
            Bs2[baseL + (lane0 + 1) * 2 + khalf] = wvl[j].y;
        }
    };

    float c[4][4][4];
#pragma unroll
    for (int i = 0; i < 4; i++)
#pragma unroll
        for (int j = 0; j < 4; j++)
#pragma unroll
            for (int k = 0; k < 4; k++) c[i][j][k] = 0.f;

    loadGlobal(0);
    storeStage(0);
    __syncthreads();

    const int KT = KDIM / BK;
    for (int kt = 0; kt < KT; kt++) {
        int stg = kt & 1;
        if (kt + 1 < KT) loadGlobal((kt + 1) * BK);

        const uint32_t* As_ = smem + stg * 4096;
        const uint32_t* Bs2 = smem + 8192 + stg * 4096;
#pragma unroll
        for (int fk = 0; fk < 2; fk++) {
            uint32_t a[4][2][4], b[4][2][2];
#pragma unroll
            for (int fm = 0; fm < 4; fm++)
#pragma unroll
                for (int pl = 0; pl < 2; pl++) {
                    uint4 v = *(const uint4*)&As_[((fk * 8 + wm * 4 + fm) * 2 + pl) * 128 + lane * 4];
                    a[fm][pl][0] = v.x; a[fm][pl][1] = v.y; a[fm][pl][2] = v.z; a[fm][pl][3] = v.w;
                }
#pragma unroll
            for (int fn = 0; fn < 4; fn++)
#pragma unroll
                for (int pl = 0; pl < 2; pl++) {
                    uint2 v = *(const uint2*)&Bs2[((fk * 16 + wn * 4 + fn) * 2 + pl) * 64 + lane * 2];
                    b[fn][pl][0] = v.x; b[fn][pl][1] = v.y;
                }
#pragma unroll
            for (int fm = 0; fm < 4; fm++)
#pragma unroll
                for (int fn = 0; fn < 4; fn++) {
                    mma_bf16(c[fm][fn], a[fm][0], b[fn][0]);
                    mma_bf16(c[fm][fn], a[fm][0], b[fn][1]);
                    mma_bf16(c[fm][fn], a[fm][1], b[fn][0]);
                }
        }
        if (kt + 1 < KT) storeStage(stg ^ 1);
        __syncthreads();
    }

    int g = lane >> 2, t = lane & 3;
#pragma unroll
    for (int fm = 0; fm < 4; fm++) {
        int mloc = wm * 64 + fm * 16 + g;
#pragma unroll
        for (int fn = 0; fn < 4; fn++) {
            int col = n0 + wn * 32 + fn * 8 + 2 * t;
            float* cc = c[fm][fn];
            if (MODE == 1) {
                int tk0 = sTok[mloc], tk1 = sTok[mloc + 8];
                if (tk0 >= 0) {
                    atomicAdd(&Cout[(size_t)tk0 * H_DIM + col], cc[0]);
                    atomicAdd(&Cout[(size_t)tk0 * H_DIM + col + 1], cc[1]);
                }
                if (tk1 >= 0) {
                    atomicAdd(&Cout[(size_t)tk1 * H_DIM + col], cc[2]);
                    atomicAdd(&Cout[(size_t)tk1 * H_DIM + col + 1], cc[3]);
                }
            } else {
                size_t r0 = (size_t)(row0 + mloc) * LDC + col;
                size_t r1 = (size_t)(row0 + mloc + 8) * LDC + col;
                *(float2*)&C[r0] = make_float2(cc[0], cc[1]);
                *(float2*)&C[r1] = make_float2(cc[2], cc[3]);
            }
        }
    }
}

// ---------------- SwiGLU -> bf16 hi/lo planes ----------------
__global__ void swiglu_routed() {
    size_t i = (size_t)blockIdx.x * 256 + threadIdx.x;
    size_t total = (size_t)PADROWS * (I_DIM / 4);
    if (i >= total) return;
    int row = (int)(i / (I_DIM / 4));
    int col = (int)(i % (I_DIM / 4)) * 4;
    size_t off = (size_t)row * I_DIM + col;
    int a = d_assign[row];
    float v[4] = {0.f, 0.f, 0.f, 0.f};
    if (a >= 0) {
        float w = d_topw[a];
        float4 gv = *(const float4*)&d_yg[off];
        float4 uv = *(const float4*)&d_yu[off];
        v[0] = (gv.x / (1.f + expf(-gv.x))) * uv.x * w;
        v[1] = (gv.y / (1.f + expf(-gv.y))) * uv.y * w;
        v[2] = (gv.z / (1.f + expf(-gv.z))) * uv.z * w;
        v[3] = (gv.w / (1.f + expf(-gv.w))) * uv.w * w;
    }
    uint2 h, l; split4(v, h, l);
    *(uint2*)(d_yh + off) = h;
    *(uint2*)(d_yl + off) = l;
}

__global__ void swiglu_shared() {
    size_t i = (size_t)blockIdx.x * 256 + threadIdx.x;
    size_t total = (size_t)T_TOK * (SH_DIM / 4);
    if (i >= total) return;
    size_t off = i * 4;
    float4 gv = *(const float4*)&d_yshg[off];
    float4 uv = *(const float4*)&d_yshu[off];
    float v[4];
    v[0] = (gv.x / (1.f + expf(-gv.x))) * uv.x;
    v[1] = (gv.y / (1.f + expf(-gv.y))) * uv.y;
    v[2] = (gv.z / (1.f + expf(-gv.z))) * uv.z;
    v[3] = (gv.w / (1.f + expf(-gv.w))) * uv.w;
    uint2 h, l; split4(v, h, l);
    *(uint2*)(d_yshh + off) = h;
    *(uint2*)(d_yshl + off) = l;
}

// ---------------- launch ----------------
extern "C" void kernel_launch(void* const* d_in, const int* in_sizes, int n_in,
                              void* d_out, int out_size) {
    const float* x   = (const float*)d_in[0];
    const float* gw  = (const float*)d_in[1];
    const int*   wqg = (const int*)d_in[2];
    const float* sg  = (const float*)d_in[3];
    const float* zg  = (const float*)d_in[4];
    const int*   wqu = (const int*)d_in[5];
    const float* su  = (const float*)d_in[6];
    const float* zu  = (const float*)d_in[7];
    const int*   wqd = (const int*)d_in[8];
    const float* sd  = (const float*)d_in[9];
    const float* zd  = (const float*)d_in[10];
    const float* wgs = (const float*)d_in[11];
    const float* wus = (const float*)d_in[12];
    const float* wds = (const float*)d_in[13];
    float* out = (float*)d_out;

    const int SMEM = 65536;
    cudaFuncSetAttribute(gemm_kernel<0>, cudaFuncAttributeMaxDynamicSharedMemorySize, SMEM);
    cudaFuncSetAttribute(gemm_kernel<1>, cudaFuncAttributeMaxDynamicSharedMemorySize, SMEM);
    cudaFuncSetAttribute(gemm_kernel<2>, cudaFuncAttributeMaxDynamicSharedMemorySize, SMEM);
    cudaFuncSetAttribute(gemm_kernel<3>, cudaFuncAttributeMaxDynamicSharedMemorySize, SMEM);

    init_kernel<<<(PADROWS + 255) / 256, 256>>>();
    gate_kernel<<<(T_TOK * 32 + 127) / 128, 128>>>(x, gw);
    scan_kernel<<<1, 1>>>();
    scatter_kernel<<<(NASS_MAX + 255) / 256, 256>>>();

    // one-shot conversions (destinations bound in device code)
    size_t q4 = (size_t)E_NUM * I_DIM * H_DIM / 4;
    unsigned qb = (unsigned)((q4 + 255) / 256);
    conv_quant<0><<<qb, 256>>>(wqg, sg, zg);
    conv_quant<1><<<qb, 256>>>(wqu, su, zu);
    conv_quant<2><<<qb, 256>>>(wqd, sd, zd);
    size_t x4 = (size_t)T_TOK * H_DIM / 4;
    conv_float<0><<<(unsigned)((x4 + 255) / 256), 256>>>(x);
    size_t s4 = (size_t)SH_DIM * H_DIM / 4;
    unsigned sb = (unsigned)((s4 + 255) / 256);
    conv_float<1><<<sb, 256>>>(wgs);
    conv_float<2><<<sb, 256>>>(wus);
    conv_float<3><<<sb, 256>>>(wds);

    // shared expert
    gemm_kernel<2><<<dim3(T_TOK / BM, SH_DIM / BN), 256, SMEM>>>(nullptr, 0);
    gemm_kernel<2><<<dim3(T_TOK / BM, SH_DIM / BN), 256, SMEM>>>(nullptr, 1);
    {
        size_t t4 = (size_t)T_TOK * SH_DIM / 4;
        swiglu_shared<<<(unsigned)((t4 + 255) / 256), 256>>>();
    }
    gemm_kernel<3><<<dim3(T_TOK / BM, H_DIM / BN), 256, SMEM>>>(out, 0);

    // routed experts
    gemm_kernel<0><<<dim3(MAXTILES, I_DIM / BN), 256, SMEM>>>(nullptr, 0);
    gemm_kernel<0><<<dim3(MAXTILES, I_DIM / BN), 256, SMEM>>>(nullptr, 1);
    {
        size_t t4 = (size_t)PADROWS * I_DIM / 4;
        swiglu_routed<<<(unsigned)((t4 + 255) / 256), 256>>>();
    }
    gemm_kernel<1><<<dim3(MAXTILES, H_DIM / BN), 256, SMEM>>>(out, 0);
}